// round 3
// baseline (speedup 1.0000x reference)
#include <cuda_runtime.h>
#include <cuda_bf16.h>
#include <cstdint>

// Problem constants (hardcoded from reference: B=8, N=128, C=256, H=8)
#define BB 8
#define NN 128
#define CC 256
#define HH 8
#define RTOT (BB*NN*NN)      // 131072 rows
#define KSEL 64              // node_num/2

typedef unsigned long long ull;

__device__ int g_pos[NN];
__device__ int g_skip;

// ---------- helpers ----------
__device__ __forceinline__ void fma2(ull &d, ull a, ull b) {
    asm("fma.rn.f32x2 %0, %1, %2, %3;" : "=l"(d) : "l"(a), "l"(b), "l"(d));
}
__device__ __forceinline__ ull addf2(ull a, ull b) {
    ull d; asm("add.rn.f32x2 %0, %1, %2;" : "=l"(d) : "l"(a), "l"(b)); return d;
}
__device__ __forceinline__ ull dup32(unsigned x) {
    ull d; asm("mov.b64 %0, {%1, %1};" : "=l"(d) : "r"(x)); return d;
}
__device__ __forceinline__ float sigmoidf_fast(float x) {
    return __fdividef(1.0f, 1.0f + __expf(-x));
}

// ---------- kernel 0: init scratch ----------
__global__ void init_kernel() {
    int t = threadIdx.x;
    if (t < NN) g_pos[t] = 0;
    if (t == 0) g_skip = 0;
}

// ---------- kernel A: attn = sigmoid(q@Wq^T + k@Wk^T + b) ----------
// One warp processes 4 consecutive rows. Lane covers c = lane + 32*cc (cc=0..7).
// W packed in smem as h-pairs for f32x2 FMA: sW[tensor][c][h2] = {W[2h2][col], W[2h2+1][col]}
__global__ void __launch_bounds__(256) attn_kernel(
    const float* __restrict__ q, const float* __restrict__ k,
    const float* __restrict__ W, const float* __restrict__ bias,
    float* __restrict__ out)
{
    __shared__ __align__(16) ull sW[2][CC][4];   // 16 KB

    int tid = threadIdx.x;
    // pack W into smem: 2 tensors * 256 c * 4 h-pairs = 2048 entries
    for (int i = tid; i < 2048; i += 256) {
        int t  = i >> 10;
        int c  = (i >> 2) & 255;
        int h2 = i & 3;
        int col = t * CC + c;                    // Wq: cols 0..255, Wk: 256..511
        unsigned lo = __float_as_uint(W[(2*h2    )*(2*CC) + col]);
        unsigned hi = __float_as_uint(W[(2*h2 + 1)*(2*CC) + col]);
        sW[t][c][h2] = ((ull)hi << 32) | lo;
    }
    __syncthreads();

    int warp = tid >> 5, lane = tid & 31;
    int base_row = (blockIdx.x * 8 + warp) * 4;
    const float* qp = q + (size_t)base_row * CC;
    const float* kp = k + (size_t)base_row * CC;

    ull acc[4][4];
    #pragma unroll
    for (int r = 0; r < 4; r++)
        #pragma unroll
        for (int h2 = 0; h2 < 4; h2++) acc[r][h2] = 0ull;

    #pragma unroll
    for (int cc = 0; cc < 8; cc++) {
        int c = lane + (cc << 5);
        ull qd[4], kd[4];
        #pragma unroll
        for (int r = 0; r < 4; r++) {
            qd[r] = dup32(__float_as_uint(qp[r*CC + c]));
            kd[r] = dup32(__float_as_uint(kp[r*CC + c]));
        }
        ulonglong2 wq01 = *reinterpret_cast<const ulonglong2*>(&sW[0][c][0]);
        ulonglong2 wq23 = *reinterpret_cast<const ulonglong2*>(&sW[0][c][2]);
        ulonglong2 wk01 = *reinterpret_cast<const ulonglong2*>(&sW[1][c][0]);
        ulonglong2 wk23 = *reinterpret_cast<const ulonglong2*>(&sW[1][c][2]);
        #pragma unroll
        for (int r = 0; r < 4; r++) {
            fma2(acc[r][0], qd[r], wq01.x);
            fma2(acc[r][1], qd[r], wq01.y);
            fma2(acc[r][2], qd[r], wq23.x);
            fma2(acc[r][3], qd[r], wq23.y);
            fma2(acc[r][0], kd[r], wk01.x);
            fma2(acc[r][1], kd[r], wk01.y);
            fma2(acc[r][2], kd[r], wk23.x);
            fma2(acc[r][3], kd[r], wk23.y);
        }
    }

    // full butterfly reduction over 32 lanes (packed f32x2 adds)
    #pragma unroll
    for (int r = 0; r < 4; r++)
        #pragma unroll
        for (int h2 = 0; h2 < 4; h2++) {
            ull v = acc[r][h2];
            #pragma unroll
            for (int off = 16; off > 0; off >>= 1)
                v = addf2(v, __shfl_xor_sync(0xffffffffu, v, off));
            acc[r][h2] = v;
        }

    // lanes 0..3 each own one h-pair; apply bias + sigmoid and store float2
    if (lane < 4) {
        float blo = bias[2*lane], bhi = bias[2*lane + 1];
        #pragma unroll
        for (int r = 0; r < 4; r++) {
            ull v = (lane == 0) ? acc[r][0] : (lane == 1) ? acc[r][1]
                  : (lane == 2) ? acc[r][2] : acc[r][3];
            float x = __uint_as_float((unsigned)v)         + blo;
            float y = __uint_as_float((unsigned)(v >> 32)) + bhi;
            x = sigmoidf_fast(x);
            y = sigmoidf_fast(y);
            *reinterpret_cast<float2*>(out + (size_t)(base_row + r)*HH + lane*2)
                = make_float2(x, y);
        }
    }
}

// ---------- kernel B: exact stable top-64 selection -> union into g_pos ----------
// One block per (b,i) pair. Warp w handles head h=w for BOTH masks.
// Key = (bits(value)<<32) | (127-j): strict u64 '>' reproduces jax.lax.top_k's
// (value desc, index asc) stable ordering; keys are distinct so rank<64 <=> selected.
__global__ void __launch_bounds__(256) topk_kernel(
    const float* __restrict__ attn,
    const float* __restrict__ m1, const float* __restrict__ m2,
    int pair_off, int use_skip)
{
    if (use_skip) {
        if (*(volatile int*)&g_skip) return;
    }
    int pair = pair_off + blockIdx.x;

    __shared__ ull sk1[HH][NN];
    __shared__ ull sk2[HH][NN];

    int tid = threadIdx.x;
    // build keys: each thread loads float4 covering (j = tid/2, h0 = (tid&1)*4)
    {
        float4 a = *reinterpret_cast<const float4*>(attn + (size_t)pair*NN*HH + tid*4);
        int j  = tid >> 1;
        int h0 = (tid & 1) * 4;
        float mm1 = __ldg(&m1[pair*NN + j]);
        float mm2 = __ldg(&m2[pair*NN + j]);
        const float* av = &a.x;
        #pragma unroll
        for (int i = 0; i < 4; i++) {
            float v = av[i];
            sk1[h0+i][j] = ((ull)__float_as_uint(v*mm1) << 32) | (ull)(127 - j);
            sk2[h0+i][j] = ((ull)__float_as_uint(v*mm2) << 32) | (ull)(127 - j);
        }
    }
    __syncthreads();

    int warp = tid >> 5, lane = tid & 31;
    int h = warp;
    ull my1[4], my2[4];
    int c1[4] = {0,0,0,0}, c2[4] = {0,0,0,0};
    #pragma unroll
    for (int r = 0; r < 4; r++) {
        int j = lane*4 + r;
        my1[r] = sk1[h][j];
        my2[r] = sk2[h][j];
    }
    #pragma unroll 4
    for (int jj = 0; jj < NN; jj++) {
        ull k1 = sk1[h][jj];
        ull k2 = sk2[h][jj];
        #pragma unroll
        for (int r = 0; r < 4; r++) {
            c1[r] += (k1 > my1[r]);
            c2[r] += (k2 > my2[r]);
        }
    }
    #pragma unroll
    for (int r = 0; r < 4; r++) {
        if (c1[r] < KSEL || c2[r] < KSEL) g_pos[lane*4 + r] = 1;
    }
}

// ---------- kernel B2: set skip flag if pos already saturated ----------
__global__ void check_kernel() {
    int ok = (g_pos[threadIdx.x] != 0);
    int all = __syncthreads_and(ok);
    if (threadIdx.x == 0) g_skip = all ? 1 : 0;
}

// ---------- kernel C: out = attn * (m1+m2) * pos[j]  (in-place) ----------
__global__ void __launch_bounds__(256) finalize_kernel(
    float* __restrict__ out,
    const float* __restrict__ m1, const float* __restrict__ m2)
{
    int gid = blockIdx.x * blockDim.x + threadIdx.x;   // row index over (b,i,j)
    int j = gid & (NN - 1);
    float f = (m1[gid] + m2[gid]) * (float)g_pos[j];
    float4* o = reinterpret_cast<float4*>(out + (size_t)gid * HH);
    float4 a = o[0], b = o[1];
    a.x *= f; a.y *= f; a.z *= f; a.w *= f;
    b.x *= f; b.y *= f; b.z *= f; b.w *= f;
    o[0] = a; o[1] = b;
}

extern "C" void kernel_launch(void* const* d_in, const int* in_sizes, int n_in,
                              void* d_out, int out_size)
{
    const float* q  = (const float*)d_in[0];
    const float* k  = (const float*)d_in[1];
    const float* m1 = (const float*)d_in[2];
    const float* m2 = (const float*)d_in[3];
    const float* W  = (const float*)d_in[4];
    const float* bv = (const float*)d_in[5];
    float* out = (float*)d_out;

    init_kernel<<<1, 128>>>();
    attn_kernel<<<RTOT / 32, 256>>>(q, k, W, bv, out);
    // honest pass over first 32 (b,i) pairs
    topk_kernel<<<32, 256>>>(out, m1, m2, 0, 0);
    check_kernel<<<1, 128>>>();
    // remaining pairs: early-return if pos already all-ones (exactness preserved:
    // union can only grow, and if saturated it cannot change)
    topk_kernel<<<BB*NN - 32, 256>>>(out, m1, m2, 32, 1);
    finalize_kernel<<<RTOT / 256, 256>>>(out, m1, m2);
}

// round 5
// speedup vs baseline: 1.0455x; 1.0455x over previous
#include <cuda_runtime.h>
#include <cuda_bf16.h>
#include <cstdint>

// Problem constants (B=8, N=128, C=256, H=8)
#define BB 8
#define NN 128
#define CC 256
#define HH 8
#define RTOT (BB*NN*NN)      // 131072 rows
#define KSEL 64              // node_num/2

typedef unsigned long long ull;

__device__ int g_pos[NN];
__device__ int g_skip;
__device__ unsigned g_cnt;

// ---------- helpers ----------
__device__ __forceinline__ void fma2(ull &d, ull a, ull b) {
    asm("fma.rn.f32x2 %0, %1, %2, %3;" : "=l"(d) : "l"(a), "l"(b), "l"(d));
}
__device__ __forceinline__ ull addf2(ull a, ull b) {
    ull d; asm("add.rn.f32x2 %0, %1, %2;" : "=l"(d) : "l"(a), "l"(b)); return d;
}
__device__ __forceinline__ ull dup32(unsigned x) {
    ull d; asm("mov.b64 %0, {%1, %1};" : "=l"(d) : "r"(x)); return d;
}
__device__ __forceinline__ float sigmoidf_fast(float x) {
    return __fdividef(1.0f, 1.0f + __expf(-x));
}

// ---------- kernel A: attn = sigmoid(q@Wq^T + k@Wk^T + b) ----------
// One warp processes 2 consecutive rows (lower regs -> higher occupancy).
// Lane covers c = lane + 32*cc (cc=0..7), coalesced 128B transactions.
// Weights in smem as flat ull array sW[((t*4+h2)<<8) | c]: lane stride 8B,
// conflict-free LDS.64.  Block 0 also zeroes the top-k scratch globals.
__global__ void __launch_bounds__(256) attn_kernel(
    const float* __restrict__ q, const float* __restrict__ k,
    const float* __restrict__ W, const float* __restrict__ bias,
    float* __restrict__ out)
{
    __shared__ __align__(16) ull sW[2048];   // 16 KB

    int tid = threadIdx.x;
    if (blockIdx.x == 0) {
        if (tid < NN) g_pos[tid] = 0;
        if (tid == 128) g_skip = 0;
        if (tid == 129) g_cnt = 0u;
    }
    // pack W: i = ((t*4+h2)<<8)|c ; pair heads (2h2, 2h2+1) for f32x2
    for (int i = tid; i < 2048; i += 256) {
        int t  = i >> 10;
        int h2 = (i >> 8) & 3;
        int c  = i & 255;
        int col = t * CC + c;                    // Wq: cols 0..255, Wk: 256..511
        unsigned lo = __float_as_uint(W[(2*h2    )*(2*CC) + col]);
        unsigned hi = __float_as_uint(W[(2*h2 + 1)*(2*CC) + col]);
        sW[i] = ((ull)hi << 32) | lo;
    }
    __syncthreads();

    int warp = tid >> 5, lane = tid & 31;
    int base_row = (blockIdx.x * 8 + warp) * 2;
    const float* qp = q + (size_t)base_row * CC;
    const float* kp = k + (size_t)base_row * CC;

    ull acc[2][4];
    #pragma unroll
    for (int r = 0; r < 2; r++)
        #pragma unroll
        for (int h2 = 0; h2 < 4; h2++) acc[r][h2] = 0ull;

    #pragma unroll
    for (int cc = 0; cc < 8; cc++) {
        int c = lane + (cc << 5);
        ull qd0 = dup32(__float_as_uint(__ldcs(qp + c)));
        ull qd1 = dup32(__float_as_uint(__ldcs(qp + CC + c)));
        ull kd0 = dup32(__float_as_uint(__ldcs(kp + c)));
        ull kd1 = dup32(__float_as_uint(__ldcs(kp + CC + c)));
        #pragma unroll
        for (int h2 = 0; h2 < 4; h2++) {
            ull wq = sW[(h2 << 8) | c];
            ull wk = sW[1024 + (h2 << 8) | c];
            fma2(acc[0][h2], qd0, wq);
            fma2(acc[1][h2], qd1, wq);
            fma2(acc[0][h2], kd0, wk);
            fma2(acc[1][h2], kd1, wk);
        }
    }

    // butterfly reduction over 32 lanes (packed f32x2 adds)
    #pragma unroll
    for (int r = 0; r < 2; r++)
        #pragma unroll
        for (int h2 = 0; h2 < 4; h2++) {
            ull v = acc[r][h2];
            #pragma unroll
            for (int off = 16; off > 0; off >>= 1)
                v = addf2(v, __shfl_xor_sync(0xffffffffu, v, off));
            acc[r][h2] = v;
        }

    // lanes 0..3 each own one h-pair; bias + sigmoid; store float2
    if (lane < 4) {
        float blo = bias[2*lane], bhi = bias[2*lane + 1];
        #pragma unroll
        for (int r = 0; r < 2; r++) {
            ull v = (lane == 0) ? acc[r][0] : (lane == 1) ? acc[r][1]
                  : (lane == 2) ? acc[r][2] : acc[r][3];
            float x = __uint_as_float((unsigned)v)         + blo;
            float y = __uint_as_float((unsigned)(v >> 32)) + bhi;
            x = sigmoidf_fast(x);
            y = sigmoidf_fast(y);
            *reinterpret_cast<float2*>(out + (size_t)(base_row + r)*HH + lane*2)
                = make_float2(x, y);
        }
    }
}

// ---------- top-k core: exact stable top-64 selection -> union into g_pos ----
// One block per (b,i) pair. Warp w handles head h=w for BOTH masks.
// Key = (bits(value)<<32) | (127-j): sigmoid output is in (0,1) and masks are
// {0,1}, so all values are non-negative floats whose IEEE bit order matches
// value order; strict u64 '>' reproduces jax.lax.top_k's (value desc, index
// asc) stable ordering; keys are distinct so rank<64 <=> selected.
__device__ __forceinline__ void topk_body(
    const float* __restrict__ attn,
    const float* __restrict__ m1, const float* __restrict__ m2,
    int pair, ull (*sk1)[NN], ull (*sk2)[NN])
{
    int tid = threadIdx.x;
    {
        float4 a = *reinterpret_cast<const float4*>(attn + (size_t)pair*NN*HH + tid*4);
        int j  = tid >> 1;
        int h0 = (tid & 1) * 4;
        float mm1 = __ldg(&m1[pair*NN + j]);
        float mm2 = __ldg(&m2[pair*NN + j]);
        const float* av = &a.x;
        #pragma unroll
        for (int i = 0; i < 4; i++) {
            float v = av[i];
            sk1[h0+i][j] = ((ull)__float_as_uint(v*mm1) << 32) | (ull)(127 - j);
            sk2[h0+i][j] = ((ull)__float_as_uint(v*mm2) << 32) | (ull)(127 - j);
        }
    }
    __syncthreads();

    int warp = tid >> 5, lane = tid & 31;
    int h = warp;
    ull my1[4], my2[4];
    int c1[4] = {0,0,0,0}, c2[4] = {0,0,0,0};
    #pragma unroll
    for (int r = 0; r < 4; r++) {
        int j = lane*4 + r;
        my1[r] = sk1[h][j];
        my2[r] = sk2[h][j];
    }
    #pragma unroll 4
    for (int jj = 0; jj < NN; jj++) {
        ull k1 = sk1[h][jj];
        ull k2 = sk2[h][jj];
        #pragma unroll
        for (int r = 0; r < 4; r++) {
            c1[r] += (k1 > my1[r]);
            c2[r] += (k2 > my2[r]);
        }
    }
    #pragma unroll
    for (int r = 0; r < 4; r++) {
        if (c1[r] < KSEL || c2[r] < KSEL) g_pos[lane*4 + r] = 1;
    }
}

// ---------- kernel B1: honest pass over first 32 pairs + saturation check ----
// Last block to finish checks whether g_pos is already all-ones and sets
// g_skip.  threadfence + atomic ordering makes earlier blocks' g_pos writes
// visible to the last block.
__global__ void __launch_bounds__(256) topk1_kernel(
    const float* __restrict__ attn,
    const float* __restrict__ m1, const float* __restrict__ m2)
{
    __shared__ ull sk1[HH][NN];
    __shared__ ull sk2[HH][NN];
    topk_body(attn, m1, m2, blockIdx.x, sk1, sk2);

    __threadfence();
    __syncthreads();
    if (threadIdx.x == 0) {
        unsigned old = atomicAdd(&g_cnt, 1u);
        if (old == 31u) {                 // last of the 32 blocks
            int all = 1;
            for (int j = 0; j < NN; j++)
                all &= (*(volatile int*)&g_pos[j] != 0);
            g_skip = all;
        }
    }
}

// ---------- kernel B2: remaining pairs, early-exit if pos saturated ----------
// Exactness preserved: the union can only grow, and once all-ones it cannot
// change, so skipping is a no-op on the result.
__global__ void __launch_bounds__(256) topk2_kernel(
    const float* __restrict__ attn,
    const float* __restrict__ m1, const float* __restrict__ m2)
{
    if (*(volatile int*)&g_skip) return;
    __shared__ ull sk1[HH][NN];
    __shared__ ull sk2[HH][NN];
    topk_body(attn, m1, m2, 32 + blockIdx.x, sk1, sk2);
}

// ---------- kernel C: out = attn * (m1+m2) * pos[j]  (in-place) ----------
__global__ void __launch_bounds__(256) finalize_kernel(
    float* __restrict__ out,
    const float* __restrict__ m1, const float* __restrict__ m2)
{
    int gid = blockIdx.x * blockDim.x + threadIdx.x;   // row index over (b,i,j)
    int j = gid & (NN - 1);
    float f = (m1[gid] + m2[gid]) * (float)g_pos[j];
    float4* o = reinterpret_cast<float4*>(out + (size_t)gid * HH);
    float4 a = o[0], b = o[1];
    a.x *= f; a.y *= f; a.z *= f; a.w *= f;
    b.x *= f; b.y *= f; b.z *= f; b.w *= f;
    o[0] = a; o[1] = b;
}

extern "C" void kernel_launch(void* const* d_in, const int* in_sizes, int n_in,
                              void* d_out, int out_size)
{
    const float* q  = (const float*)d_in[0];
    const float* k  = (const float*)d_in[1];
    const float* m1 = (const float*)d_in[2];
    const float* m2 = (const float*)d_in[3];
    const float* W  = (const float*)d_in[4];
    const float* bv = (const float*)d_in[5];
    float* out = (float*)d_out;

    attn_kernel<<<RTOT / 16, 256>>>(q, k, W, bv, out);
    topk1_kernel<<<32, 256>>>(out, m1, m2);
    topk2_kernel<<<BB*NN - 32, 256>>>(out, m1, m2);
    finalize_kernel<<<RTOT / 256, 256>>>(out, m1, m2);
}